// round 8
// baseline (speedup 1.0000x reference)
#include <cuda_runtime.h>

// SAXS P(r) L1 loss — Round 4: NO atomics on the hot path.
// Each of 128 threads per block owns a PRIVATE smem histogram, laid out
// word*512 + tid*4 (bank == tid&31 -> always conflict-free, race-free),
// updated with plain LDS+IADD+STS. Soft-bin pair (lo,lo+1) packs into one
// u32 as two u16 fields (scale 256): hist[lo] += (256-q) | (q<<16).
// Blocks are persistent over ~10 atom-tile pairs (grid 296 x 2 structures,
// 2 blocks/SM), double-buffered tile prefetch, one flush per block.

namespace {
constexpr int   kNBins      = 201;
constexpr int   kNAtoms     = 9472;                       // 256*37
constexpr int   kTile       = 128;
constexpr int   kNTiles     = kNAtoms / kTile;            // 74
constexpr int   kNPairTiles = kNTiles * (kNTiles + 1) / 2;   // 2775
constexpr int   kBlocksX    = 296;                        // tile stride per block
constexpr float kPre        = 512.0f;                     // 256 / STEP (STEP=0.5)
constexpr float kClampIT    = 51711.0f;                   // word<=201 (trash)
constexpr int   kWords      = 204;                        // 201 bins + trash + pad
constexpr int   kHistBytes  = kWords * 128 * 4;           // 104448
constexpr int   kSmemBytes  = kHistBytes + 2 * 256 * 16;  // + ping-pong tiles
}

__device__ float4       g_pos[2][kNAtoms];   // prescaled (x,y,z,-)
__device__ unsigned int g_hist[2][256];      // fixed-point (scale 256) totals

// ---------------------------------------------------------------------------
__global__ void prepack_kernel(const float* __restrict__ pred,
                               const float* __restrict__ tru,
                               const float* __restrict__ mask) {
    int i = blockIdx.x * blockDim.x + threadIdx.x;
    if (i < 512) ((unsigned int*)g_hist)[i] = 0u;
    if (i >= kNAtoms) return;
    float m = mask[i];
    if (m != 0.0f) {
        g_pos[0][i] = make_float4(pred[3*i+0]*kPre, pred[3*i+1]*kPre, pred[3*i+2]*kPre, 0.f);
        g_pos[1][i] = make_float4(tru [3*i+0]*kPre, tru [3*i+1]*kPre, tru [3*i+2]*kPre, 0.f);
    } else {
        // Displace masked atoms: all their pair distances exceed the clamp ->
        // trash word 201, excluded from flush.
        float dx = 1.0e8f + (float)i * 2.0e5f;
        g_pos[0][i] = make_float4(dx, 0.f, 0.f, 0.f);
        g_pos[1][i] = make_float4(dx, 0.f, 0.f, 0.f);
    }
}

// ---------------------------------------------------------------------------
__device__ __forceinline__ void decode_tile(int p, int& bi, int& bj) {
    double Td = (double)kNTiles;
    int b = (int)(((2.0 * Td + 1.0) -
                   sqrt((2.0 * Td + 1.0) * (2.0 * Td + 1.0) - 8.0 * (double)p)) * 0.5);
    if (b < 0) b = 0;
    if (b > kNTiles - 1) b = kNTiles - 1;
    while (b * (2 * kNTiles - b + 1) / 2 > p) --b;
    while ((b + 1) * (2 * kNTiles - b) / 2 <= p) ++b;
    bi = b;
    bj = b + (p - b * (2 * kNTiles - b + 1) / 2);
}

// ---------------------------------------------------------------------------
__global__ __launch_bounds__(128, 2)
void pair_hist_kernel() {
    extern __shared__ unsigned int smem[];
    unsigned int* hist = smem;                              // [204][128] u32
    float4* buf = (float4*)(smem + kWords * 128);           // [2][256] float4

    const int s   = blockIdx.y;
    const int tid = threadIdx.x;
    const int tx  = tid & 15;      // col group: cols tx*8 + v
    const int ty  = tid >> 4;      // row group: rows ty*16 + u

    // Zero private histograms (conflict-free columns).
#pragma unroll 4
    for (int w = 0; w < kWords; ++w) hist[(w << 7) + tid] = 0u;

    // Prefetch first tile pair.
    int p = blockIdx.x;
    int bi, bj;
    decode_tile(p, bi, bj);
    float4 a = g_pos[s][bi * kTile + tid];
    float4 b = g_pos[s][bj * kTile + tid];
    int cur = 0;
    buf[tid]       = a;
    buf[128 + tid] = b;
    __syncthreads();

    for (;;) {
        const int pn = p + kBlocksX;
        const bool havenext = (pn < kNPairTiles);
        float4 an, bn; int bin_ = 0, bjn = 0;
        if (havenext) {
            decode_tile(pn, bin_, bjn);
            an = g_pos[s][bin_ * kTile + tid];
            bn = g_pos[s][bjn * kTile + tid];
        }

        // ---- compute 16x8 register sub-tile of the 128x128 pair tile ----
        const float4* ti = buf + cur * 256;
        const float4* tj = ti + 128;
        float3 ri[16], rj[8];
#pragma unroll
        for (int u = 0; u < 16; ++u) {
            float4 t4 = ti[ty * 16 + u];
            ri[u] = make_float3(t4.x, t4.y, t4.z);
        }
#pragma unroll
        for (int v = 0; v < 8; ++v) {
            float4 t4 = tj[tx * 8 + v];
            rj[v] = make_float3(t4.x, t4.y, t4.z);
        }

        if (bi != bj) {
#pragma unroll
            for (int u = 0; u < 16; ++u) {
#pragma unroll
                for (int v = 0; v < 8; ++v) {
                    float dx = ri[u].x - rj[v].x;
                    float dy = ri[u].y - rj[v].y;
                    float dz = ri[u].z - rj[v].z;
                    float d2 = fmaf(dx, dx, fmaf(dy, dy, dz * dz));
                    d2 = fmaxf(d2, 2.62144e-7f);            // 1e-12 * 512^2
                    float t = fminf(d2 * rsqrtf(d2), kClampIT);  // d*256/STEP
                    int it = (int)t;
                    int word = it >> 8;
                    unsigned q = (unsigned)(it & 255);
                    unsigned val = (256u - q) + (q << 16);  // IMAD q,65535,256
                    hist[(word << 7) + tid] += val;         // private: no race
                }
            }
        } else {
#pragma unroll
            for (int u = 0; u < 16; ++u) {
                const int iu = ty * 16 + u;
#pragma unroll
                for (int v = 0; v < 8; ++v) {
                    const int jv = tx * 8 + v;
                    float dx = ri[u].x - rj[v].x;
                    float dy = ri[u].y - rj[v].y;
                    float dz = ri[u].z - rj[v].z;
                    float d2 = fmaf(dx, dx, fmaf(dy, dy, dz * dz));
                    d2 = fmaxf(d2, 2.62144e-7f);
                    float t = fminf(d2 * rsqrtf(d2), kClampIT);
                    int it = (int)t;
                    if (iu >= jv) it = 203 << 8;            // trash word
                    int word = it >> 8;
                    unsigned q = (unsigned)(it & 255);
                    unsigned val = (256u - q) + (q << 16);
                    hist[(word << 7) + tid] += val;
                }
            }
        }

        __syncthreads();
        if (!havenext) break;
        buf[(cur ^ 1) * 256 + tid]       = an;
        buf[(cur ^ 1) * 256 + 128 + tid] = bn;
        __syncthreads();
        cur ^= 1; p = pn; bi = bin_; bj = bjn;
    }

    // ---- flush: bin b total = sum_t low(hist[b][t]) + high(hist[b-1][t]) ----
    unsigned int* shh = (unsigned int*)buf;   // 204 u32 scratch
    unsigned slo_c[2];
#pragma unroll
    for (int c = 0; c < 2; ++c) {
        int w = tid + c * 128;
        unsigned slo = 0, shi = 0;
        if (w < kWords) {
            for (int i = 0; i < 128; ++i) {
                int t = (tid + i) & 127;                    // stagger: no conflicts
                unsigned v = hist[(w << 7) + t];
                slo += v & 0xFFFFu;
                shi += v >> 16;
            }
            shh[w] = shi;
        }
        slo_c[c] = slo;
    }
    __syncthreads();
#pragma unroll
    for (int c = 0; c < 2; ++c) {
        int w = tid + c * 128;
        if (w <= 200) {
            unsigned total = slo_c[c]
                           + (w > 0 ? shh[w - 1] : 0u)
                           + (w == 200 ? shh[200] : 0u);    // ref clips bin 201 -> 200
            if (total) atomicAdd(&g_hist[s][w], total);
        }
    }
}

// ---------------------------------------------------------------------------
__global__ void finalize_kernel(float* __restrict__ out) {
    __shared__ double sh[256];
    const int tid = threadIdx.x;
    double h0 = (tid < kNBins) ? (double)g_hist[0][tid] : 0.0;
    double h1 = (tid < kNBins) ? (double)g_hist[1][tid] : 0.0;

    sh[tid] = h0; __syncthreads();
    for (int o = 128; o > 0; o >>= 1) { if (tid < o) sh[tid] += sh[tid + o]; __syncthreads(); }
    double s0 = sh[0]; __syncthreads();

    sh[tid] = h1; __syncthreads();
    for (int o = 128; o > 0; o >>= 1) { if (tid < o) sh[tid] += sh[tid + o]; __syncthreads(); }
    double s1 = sh[0]; __syncthreads();

    sh[tid] = fabs(h0 / (s0 + 1e-12) - h1 / (s1 + 1e-12)); __syncthreads();
    for (int o = 128; o > 0; o >>= 1) { if (tid < o) sh[tid] += sh[tid + o]; __syncthreads(); }

    if (tid == 0) out[0] = (float)sh[0];
}

// ---------------------------------------------------------------------------
extern "C" void kernel_launch(void* const* d_in, const int* in_sizes, int n_in,
                              void* d_out, int out_size) {
    (void)in_sizes; (void)n_in; (void)out_size;
    const float* pred = (const float*)d_in[0];
    const float* tru  = (const float*)d_in[1];
    const float* mask = (const float*)d_in[2];

    cudaFuncSetAttribute(pair_hist_kernel,
                         cudaFuncAttributeMaxDynamicSharedMemorySize, kSmemBytes);

    prepack_kernel<<<(kNAtoms + 255) / 256, 256>>>(pred, tru, mask);

    dim3 grid(kBlocksX, 2);
    pair_hist_kernel<<<grid, 128, kSmemBytes>>>();

    finalize_kernel<<<1, 256>>>((float*)d_out);
}

// round 9
// speedup vs baseline: 1.0829x; 1.0829x over previous
#include <cuda_runtime.h>

// SAXS P(r) L1 loss — Round 5.
// vs R4: (a) magic-number rounding replaces F2I (word+q straight from float
// bits); (b) per-pair RMW batched 2-wide with equal-offset merge (conflicting
// update folded, second redirected to excluded trash word) -> MLP=2 on the
// 29-cyc LDS chain; (c) fmaxf dropped; (d) u-loop unrolled 4x only (I$).
// Private per-thread smem histograms (bank == tid&31, conflict-free, raceless).

namespace {
constexpr int   kNBins      = 201;
constexpr int   kNAtoms     = 9472;                       // 256*37
constexpr int   kTile       = 128;
constexpr int   kNTiles     = kNAtoms / kTile;            // 74
constexpr int   kNPairTiles = kNTiles * (kNTiles + 1) / 2;   // 2775
constexpr int   kBlocksX    = 296;
constexpr float kPre        = 512.0f;                     // 256 / STEP
constexpr float kClampT     = 51711.0f;                   // word 201 (trash)
constexpr int   kWords      = 204;                        // 0..200 live, 201-203 trash
constexpr int   kHistBytes  = kWords * 128 * 4;           // 104448
constexpr int   kSmemBytes  = kHistBytes + 2 * 256 * 16;
constexpr unsigned kMergeTrash = 202u << 9;               // byte offset, word 202
constexpr unsigned kDiagTrash  = 203u << 9;               // byte offset, word 203
}

__device__ float4       g_pos[2][kNAtoms];
__device__ unsigned int g_hist[2][256];

// ---------------------------------------------------------------------------
__global__ void prepack_kernel(const float* __restrict__ pred,
                               const float* __restrict__ tru,
                               const float* __restrict__ mask) {
    int i = blockIdx.x * blockDim.x + threadIdx.x;
    if (i < 512) ((unsigned int*)g_hist)[i] = 0u;
    if (i >= kNAtoms) return;
    float m = mask[i];
    if (m != 0.0f) {
        g_pos[0][i] = make_float4(pred[3*i+0]*kPre, pred[3*i+1]*kPre, pred[3*i+2]*kPre, 0.f);
        g_pos[1][i] = make_float4(tru [3*i+0]*kPre, tru [3*i+1]*kPre, tru [3*i+2]*kPre, 0.f);
    } else {
        float dx = 1.0e8f + (float)i * 2.0e5f;   // displaced -> clamp -> trash word
        g_pos[0][i] = make_float4(dx, 0.f, 0.f, 0.f);
        g_pos[1][i] = make_float4(dx, 0.f, 0.f, 0.f);
    }
}

// ---------------------------------------------------------------------------
__device__ __forceinline__ void decode_tile(int p, int& bi, int& bj) {
    double Td = (double)kNTiles;
    int b = (int)(((2.0 * Td + 1.0) -
                   sqrt((2.0 * Td + 1.0) * (2.0 * Td + 1.0) - 8.0 * (double)p)) * 0.5);
    if (b < 0) b = 0;
    if (b > kNTiles - 1) b = kNTiles - 1;
    while (b * (2 * kNTiles - b + 1) / 2 > p) --b;
    while ((b + 1) * (2 * kNTiles - b) / 2 <= p) ++b;
    bi = b;
    bj = b + (p - b * (2 * kNTiles - b + 1) / 2);
}

// Compute (byte-offset, packed val) for one pair.
__device__ __forceinline__ void pair_ov(float ax, float ay, float az,
                                        const float3 rj,
                                        unsigned& off, unsigned& val) {
    float dx = ax - rj.x;
    float dy = ay - rj.y;
    float dz = az - rj.z;
    float d2 = fmaf(dx, dx, fmaf(dy, dy, dz * dz));
    float t  = fminf(d2 * rsqrtf(d2), kClampT);      // d * 256/STEP; NaN -> clamp
    int   b  = __float_as_int(t + 12582912.0f);      // rn(t) in low mantissa bits
    unsigned q = (unsigned)b & 255u;
    off = ((unsigned)b & 0xFF00u) << 1;              // word * 512 bytes
    val = q * 65535u + 256u;                         // (256-q) | (q<<16)
}

// Batched 2-wide RMW with conflict merge (lost-update safe).
__device__ __forceinline__ void rmw2(char* hb, unsigned off0, unsigned val0,
                                     unsigned off1, unsigned val1) {
    if (off0 == off1) { val0 += val1; off1 = kMergeTrash; }  // word 202: excluded
    unsigned a0 = *(unsigned*)(hb + off0);
    unsigned a1 = *(unsigned*)(hb + off1);
    *(unsigned*)(hb + off0) = a0 + val0;
    *(unsigned*)(hb + off1) = a1 + val1;
}

// ---------------------------------------------------------------------------
__global__ __launch_bounds__(128, 2)
void pair_hist_kernel() {
    extern __shared__ unsigned int smem[];
    unsigned int* hist = smem;                              // [204][128]
    float4* buf = (float4*)(smem + kWords * 128);           // [2][256] float4

    const int s   = blockIdx.y;
    const int tid = threadIdx.x;
    const int tx  = tid & 15;
    const int ty  = tid >> 4;
    char* hb = (char*)hist + tid * 4;                       // bank = tid&31

#pragma unroll 4
    for (int w = 0; w < kWords; ++w) hist[(w << 7) + tid] = 0u;

    int p = blockIdx.x;
    int bi, bj;
    decode_tile(p, bi, bj);
    float4 a = g_pos[s][bi * kTile + tid];
    float4 b = g_pos[s][bj * kTile + tid];
    int cur = 0;
    buf[tid]       = a;
    buf[128 + tid] = b;
    __syncthreads();

    for (;;) {
        const int pn = p + kBlocksX;
        const bool havenext = (pn < kNPairTiles);
        float4 an, bn; int bin_ = 0, bjn = 0;
        if (havenext) {
            decode_tile(pn, bin_, bjn);
            an = g_pos[s][bin_ * kTile + tid];
            bn = g_pos[s][bjn * kTile + tid];
        }

        const float4* ti = buf + cur * 256;
        const float4* tj = ti + 128;
        float3 rj[8];
#pragma unroll
        for (int v = 0; v < 8; ++v) {
            float4 t4 = tj[tx * 8 + v];
            rj[v] = make_float3(t4.x, t4.y, t4.z);
        }

        if (bi != bj) {
            for (int u0 = 0; u0 < 16; u0 += 4) {
#pragma unroll
                for (int uu = 0; uu < 4; ++uu) {
                    float4 a4 = ti[ty * 16 + u0 + uu];
#pragma unroll
                    for (int v = 0; v < 8; v += 2) {
                        unsigned o0, v0, o1, v1;
                        pair_ov(a4.x, a4.y, a4.z, rj[v],     o0, v0);
                        pair_ov(a4.x, a4.y, a4.z, rj[v + 1], o1, v1);
                        rmw2(hb, o0, v0, o1, v1);
                    }
                }
            }
        } else {
            for (int u0 = 0; u0 < 16; u0 += 4) {
#pragma unroll
                for (int uu = 0; uu < 4; ++uu) {
                    const int iu = ty * 16 + u0 + uu;
                    float4 a4 = ti[iu];
#pragma unroll
                    for (int v = 0; v < 8; v += 2) {
                        unsigned o0, v0, o1, v1;
                        pair_ov(a4.x, a4.y, a4.z, rj[v],     o0, v0);
                        pair_ov(a4.x, a4.y, a4.z, rj[v + 1], o1, v1);
                        if (iu >= tx * 8 + v)     o0 = kDiagTrash;   // word 203
                        if (iu >= tx * 8 + v + 1) o1 = kDiagTrash;
                        rmw2(hb, o0, v0, o1, v1);
                    }
                }
            }
        }

        __syncthreads();
        if (!havenext) break;
        buf[(cur ^ 1) * 256 + tid]       = an;
        buf[(cur ^ 1) * 256 + 128 + tid] = bn;
        __syncthreads();
        cur ^= 1; p = pn; bi = bin_; bj = bjn;
    }

    // ---- flush: bin b = sum_t low(hist[b][t]) + high(hist[b-1][t]) ----
    unsigned int* shh = (unsigned int*)buf;
    unsigned slo_c[2];
#pragma unroll
    for (int c = 0; c < 2; ++c) {
        int w = tid + c * 128;
        unsigned slo = 0, shi = 0;
        if (w < kWords) {
            for (int i = 0; i < 128; ++i) {
                int t = (tid + i) & 127;
                unsigned v = hist[(w << 7) + t];
                slo += v & 0xFFFFu;
                shi += v >> 16;
            }
            shh[w] = shi;
        }
        slo_c[c] = slo;
    }
    __syncthreads();
#pragma unroll
    for (int c = 0; c < 2; ++c) {
        int w = tid + c * 128;
        if (w <= 200) {
            unsigned total = slo_c[c]
                           + (w > 0 ? shh[w - 1] : 0u)
                           + (w == 200 ? shh[200] : 0u);   // ref clips bin201->200
            if (total) atomicAdd(&g_hist[s][w], total);
        }
    }
}

// ---------------------------------------------------------------------------
__global__ void finalize_kernel(float* __restrict__ out) {
    __shared__ double sh[256];
    const int tid = threadIdx.x;
    double h0 = (tid < kNBins) ? (double)g_hist[0][tid] : 0.0;
    double h1 = (tid < kNBins) ? (double)g_hist[1][tid] : 0.0;

    sh[tid] = h0; __syncthreads();
    for (int o = 128; o > 0; o >>= 1) { if (tid < o) sh[tid] += sh[tid + o]; __syncthreads(); }
    double s0 = sh[0]; __syncthreads();

    sh[tid] = h1; __syncthreads();
    for (int o = 128; o > 0; o >>= 1) { if (tid < o) sh[tid] += sh[tid + o]; __syncthreads(); }
    double s1 = sh[0]; __syncthreads();

    sh[tid] = fabs(h0 / (s0 + 1e-12) - h1 / (s1 + 1e-12)); __syncthreads();
    for (int o = 128; o > 0; o >>= 1) { if (tid < o) sh[tid] += sh[tid + o]; __syncthreads(); }

    if (tid == 0) out[0] = (float)sh[0];
}

// ---------------------------------------------------------------------------
extern "C" void kernel_launch(void* const* d_in, const int* in_sizes, int n_in,
                              void* d_out, int out_size) {
    (void)in_sizes; (void)n_in; (void)out_size;
    const float* pred = (const float*)d_in[0];
    const float* tru  = (const float*)d_in[1];
    const float* mask = (const float*)d_in[2];

    cudaFuncSetAttribute(pair_hist_kernel,
                         cudaFuncAttributeMaxDynamicSharedMemorySize, kSmemBytes);

    prepack_kernel<<<(kNAtoms + 255) / 256, 256>>>(pred, tru, mask);

    dim3 grid(kBlocksX, 2);
    pair_hist_kernel<<<grid, 128, kSmemBytes>>>();

    finalize_kernel<<<1, 256>>>((float*)d_out);
}